// round 12
// baseline (speedup 1.0000x reference)
#include <cuda_runtime.h>
#include <cuda_bf16.h>
#include <cooperative_groups.h>
#include <cstdint>

namespace cg = cooperative_groups;

#define NMAX   131072      // B*INPUT_LEN
#define ILEN   4096
#define PLEN   1024
#define WTOT   (NMAX / ILEN * PLEN)   // 32768 output elements

// Scratch (__device__ globals; allocation forbidden).
// INVARIANT: g_deg all-zero at entry (.bss at load; re-zeroed in phase F).
__device__ float  g_deg [NMAX];
__device__ float  g_dinv[NMAX];
__device__ float4 g_hs  [NMAX];   // raw h = x@W1, then h*dinv after phase B
__device__ float4 g_agg1[NMAX];   // layer1 unnormalized aggregator
__device__ float  g_t   [NMAX];   // layer2 pre-scaled messages t = h2*dinv
__device__ float  g_u   [WTOT];   // layer2 window accumulator

// ---------------------------------------------------------------------------
typedef unsigned long long ull;

__device__ __forceinline__ ull fma2(ull a, ull b, ull c) {
    ull d;
    asm("fma.rn.f32x2 %0, %1, %2, %3;" : "=l"(d) : "l"(a), "l"(b), "l"(c));
    return d;
}
__device__ __forceinline__ ull add2(ull a, ull b) {
    ull d;
    asm("add.rn.f32x2 %0, %1, %2;" : "=l"(d) : "l"(a), "l"(b));
    return d;
}
__device__ __forceinline__ ull pack2(float lo, float hi) {
    ull d;
    asm("mov.b64 %0, {%1, %2};" : "=l"(d) : "f"(lo), "f"(hi));
    return d;
}
__device__ __forceinline__ void unpack2(ull v, float& lo, float& hi) {
    asm("mov.b64 {%0, %1}, %2;" : "=f"(lo), "=f"(hi) : "l"(v));
}
__device__ __forceinline__ void red4(float4* p, float a, float b, float c) {
    size_t q = __cvta_generic_to_global(p);
    asm volatile("red.global.add.v4.f32 [%0], {%1, %2, %3, %4};"
                 :: "l"(q), "f"(a), "f"(b), "f"(c), "f"(0.0f) : "memory");
}

// ---------------------------------------------------------------------------
// Monolithic cooperative kernel: all 6 pipeline phases, grid.sync between.
__global__ __launch_bounds__(256)
void k_mono(const longlong2* __restrict__ Xll,
            const float* __restrict__ W1,
            const float* __restrict__ b1,
            const float* __restrict__ W2,
            const float* __restrict__ b2,
            const int* __restrict__ ei,
            float* __restrict__ out,
            int N, int E) {
    cg::grid_group gg = cg::this_grid();
    const int nb   = gridDim.x;
    const int T    = blockDim.x;
    const int gtid = blockIdx.x * T + threadIdx.x;
    const int gsz  = nb * T;
    const int* dst = ei + E;
    const int E4   = E >> 2;

    // ======== Phase A: degree histogram (1/3 of blocks) || x@W1 (2/3) ======
    int degB = nb / 3;
    if (degB < 1) degB = 1;
    if (blockIdx.x < degB) {
        int stride = degB * T;
        int i = blockIdx.x * T + threadIdx.x;
        const int4* dst4 = (const int4*)dst;
        for (int e = i; e < E4; e += stride) {
            int4 d = dst4[e];
            atomicAdd(&g_deg[d.x], 1.0f);
            atomicAdd(&g_deg[d.y], 1.0f);
            atomicAdd(&g_deg[d.z], 1.0f);
            atomicAdd(&g_deg[d.w], 1.0f);
        }
        for (int e = (E4 << 2) + i; e < E; e += stride)
            atomicAdd(&g_deg[dst[e]], 1.0f);
    } else {
        // linear path: 16 lanes per node, 4 nodes per warp iteration
        int lane = threadIdx.x & 31;
        int sub  = lane & 15;
        int half = lane >> 4;
        int warp = (((blockIdx.x - degB) * T) + threadIdx.x) >> 5;
        int nwarps = ((nb - degB) * T) >> 5;

        ull wp[4][3][2];
#pragma unroll
        for (int j = 0; j < 4; j++) {
            int c = sub + 16 * j;
#pragma unroll
            for (int k = 0; k < 3; k++) {
                wp[j][k][0] = pack2(W1[(4 * c + 0) * 3 + k], W1[(4 * c + 1) * 3 + k]);
                wp[j][k][1] = pack2(W1[(4 * c + 2) * 3 + k], W1[(4 * c + 3) * 3 + k]);
            }
        }

        int NG = N >> 2;
        for (int g = warp; g < NG; g += nwarps) {
            int nA = 4 * g + half;
            int nB = nA + 2;
            longlong2 va[4], vb[4];
            size_t baseA = (size_t)nA * 64 + sub;
            size_t baseB = (size_t)nB * 64 + sub;
#pragma unroll
            for (int j = 0; j < 4; j++) va[j] = Xll[baseA + 16 * j];
#pragma unroll
            for (int j = 0; j < 4; j++) vb[j] = Xll[baseB + 16 * j];

            ull aA0 = 0, aA1 = 0, aA2 = 0, aB0 = 0, aB1 = 0, aB2 = 0;
#pragma unroll
            for (int j = 0; j < 4; j++) {
                ull alo = (ull)va[j].x, ahi = (ull)va[j].y;
                ull blo = (ull)vb[j].x, bhi = (ull)vb[j].y;
                aA0 = fma2(alo, wp[j][0][0], aA0);  aA0 = fma2(ahi, wp[j][0][1], aA0);
                aA1 = fma2(alo, wp[j][1][0], aA1);  aA1 = fma2(ahi, wp[j][1][1], aA1);
                aA2 = fma2(alo, wp[j][2][0], aA2);  aA2 = fma2(ahi, wp[j][2][1], aA2);
                aB0 = fma2(blo, wp[j][0][0], aB0);  aB0 = fma2(bhi, wp[j][0][1], aB0);
                aB1 = fma2(blo, wp[j][1][0], aB1);  aB1 = fma2(bhi, wp[j][1][1], aB1);
                aB2 = fma2(blo, wp[j][2][0], aB2);  aB2 = fma2(bhi, wp[j][2][1], aB2);
            }
            float t0, t1;
            unpack2(aA0, t0, t1); float hA0 = t0 + t1;
            unpack2(aA1, t0, t1); float hA1 = t0 + t1;
            unpack2(aA2, t0, t1); float hA2 = t0 + t1;
            unpack2(aB0, t0, t1); float hB0 = t0 + t1;
            unpack2(aB1, t0, t1); float hB1 = t0 + t1;
            unpack2(aB2, t0, t1); float hB2 = t0 + t1;
            ull pA = pack2(hA0, hA1);
            ull pB = pack2(hB0, hB1);
#pragma unroll
            for (int off = 8; off; off >>= 1) {
                ull qA = __shfl_xor_sync(0xffffffffu, pA, off);
                ull qB = __shfl_xor_sync(0xffffffffu, pB, off);
                float rA = __shfl_xor_sync(0xffffffffu, hA2, off);
                float rB = __shfl_xor_sync(0xffffffffu, hB2, off);
                pA = add2(pA, qA);
                pB = add2(pB, qB);
                hA2 += rA;
                hB2 += rB;
            }
            if (sub == 0) {
                float x0, x1;
                unpack2(pA, x0, x1);
                g_hs[nA] = make_float4(x0, x1, hA2, 0.0f);
                unpack2(pB, x0, x1);
                g_hs[nB] = make_float4(x0, x1, hB2, 0.0f);
            }
        }
    }
    gg.sync();

    // ======== Phase B: node pass ==========================================
    for (int n = gtid; n < N; n += gsz) {
        float dv = rsqrtf(g_deg[n] + 1.0f);
        g_dinv[n] = dv;
        float4 h = g_hs[n];
        float4 hs = make_float4(h.x * dv, h.y * dv, h.z * dv, 0.0f);
        g_hs[n] = hs;
        g_agg1[n] = hs;
    }
    gg.sync();

    // ======== Phase C: layer-1 scatter ====================================
    {
        const int4* s4 = (const int4*)ei;
        const int4* d4 = (const int4*)dst;
        for (int e = gtid; e < E4; e += gsz) {
            int4 s = s4[e];
            int4 d = d4[e];
            float4 h0 = g_hs[s.x];
            float4 h1 = g_hs[s.y];
            float4 h2 = g_hs[s.z];
            float4 h3 = g_hs[s.w];
            red4(&g_agg1[d.x], h0.x, h0.y, h0.z);
            red4(&g_agg1[d.y], h1.x, h1.y, h1.z);
            red4(&g_agg1[d.z], h2.x, h2.y, h2.z);
            red4(&g_agg1[d.w], h3.x, h3.y, h3.z);
        }
        for (int e = (E4 << 2) + gtid; e < E; e += gsz) {
            int s = ei[e], d = dst[e];
            float4 h = g_hs[s];
            red4(&g_agg1[d], h.x, h.y, h.z);
        }
    }
    gg.sync();

    // ======== Phase D: finalize layer1 + seed window ======================
    {
        float b10 = b1[0], b11 = b1[1], b12 = b1[2];
        float w0 = W2[0], w1 = W2[1], w2 = W2[2];
        for (int n = gtid; n < N; n += gsz) {
            float dv = g_dinv[n];
            float4 a = g_agg1[n];
            float o0 = fmaxf(a.x * dv + b10, 0.0f);
            float o1 = fmaxf(a.y * dv + b11, 0.0f);
            float o2 = fmaxf(a.z * dv + b12, 0.0f);
            float h2 = o0 * w0 + o1 * w1 + o2 * w2;
            float t = h2 * dv;
            g_t[n] = t;
            int r = n & (ILEN - 1);
            if (r < PLEN)
                g_u[(n >> 12) * PLEN + r] = t;
        }
    }
    gg.sync();

    // ======== Phase E: layer-2 scatter (window-filtered) ==================
    {
        const int4* s4 = (const int4*)ei;
        const int4* d4 = (const int4*)dst;
        for (int e = gtid; e < E4; e += gsz) {
            int4 d = d4[e];
            int r0 = d.x & (ILEN - 1);
            int r1 = d.y & (ILEN - 1);
            int r2 = d.z & (ILEN - 1);
            int r3 = d.w & (ILEN - 1);
            if ((r0 < PLEN) | (r1 < PLEN) | (r2 < PLEN) | (r3 < PLEN)) {
                int4 s = s4[e];
                if (r0 < PLEN) atomicAdd(&g_u[(d.x >> 12) * PLEN + r0], g_t[s.x]);
                if (r1 < PLEN) atomicAdd(&g_u[(d.y >> 12) * PLEN + r1], g_t[s.y]);
                if (r2 < PLEN) atomicAdd(&g_u[(d.z >> 12) * PLEN + r2], g_t[s.z]);
                if (r3 < PLEN) atomicAdd(&g_u[(d.w >> 12) * PLEN + r3], g_t[s.w]);
            }
        }
        for (int e = (E4 << 2) + gtid; e < E; e += gsz) {
            int d = dst[e];
            int r = d & (ILEN - 1);
            if (r < PLEN)
                atomicAdd(&g_u[(d >> 12) * PLEN + r], g_t[ei[e]]);
        }
    }
    gg.sync();

    // ======== Phase F: output + restore g_deg invariant ===================
    {
        float bb = b2[0];
        for (int i = gtid; i < N; i += gsz) {
            g_deg[i] = 0.0f;
            if (i < WTOT) {
                int n = (i >> 10) * ILEN + (i & (PLEN - 1));
                out[i] = g_u[i] * g_dinv[n] + bb;
            }
        }
    }
}

// ---------------------------------------------------------------------------
extern "C" void kernel_launch(void* const* d_in, const int* in_sizes, int n_in,
                              void* d_out, int out_size) {
    const float* X   = (const float*)d_in[0];   // [N,256]
    const float* W1  = (const float*)d_in[1];   // [256,3]
    const float* b1  = (const float*)d_in[2];   // [3]
    const float* W2  = (const float*)d_in[3];   // [3,1]
    const float* b2  = (const float*)d_in[4];   // [1]
    const int*   ei  = (const int*)d_in[5];     // [2,E]
    float*       out = (float*)d_out;

    int N = in_sizes[0] / 256;
    int E = in_sizes[5] / 2;

    const int T = 256;
    int dev = 0;
    cudaGetDevice(&dev);
    int sms = 148;
    cudaDeviceGetAttribute(&sms, cudaDevAttrMultiProcessorCount, dev);
    int per = 1;
    cudaOccupancyMaxActiveBlocksPerMultiprocessor(&per, (const void*)k_mono,
                                                  T, 0);
    if (per < 1) per = 1;
    int grid = sms * per;

    const longlong2* Xll = (const longlong2*)X;
    void* args[] = { (void*)&Xll, (void*)&W1, (void*)&b1, (void*)&W2,
                     (void*)&b2, (void*)&ei, (void*)&out, &N, &E };
    cudaLaunchCooperativeKernel((const void*)k_mono, dim3(grid), dim3(T),
                                args, 0, (cudaStream_t)0);
}

// round 13
// speedup vs baseline: 1.1218x; 1.1218x over previous
#include <cuda_runtime.h>
#include <cuda_bf16.h>
#include <cstdint>

#define NMAX   131072      // B*INPUT_LEN
#define ILEN   4096
#define PLEN   1024
#define WTOT   (NMAX / ILEN * PLEN)   // 32768 output elements

// Scratch (__device__ globals; allocation forbidden).
// INVARIANT: g_deg is all-zero at kernel_launch entry. It is zero at module
// load (.bss), and k_out re-zeroes it at the end of every execution, so every
// graph replay (and any sequential re-execution) sees the same state.
__device__ float  g_deg [NMAX];
__device__ float  g_dinv[NMAX];
__device__ float4 g_hs  [NMAX];   // raw h = x@W1, then h*dinv after k_node
__device__ float4 g_agg1[NMAX];   // layer1 unnormalized aggregator
__device__ float  g_t   [NMAX];   // layer2 pre-scaled messages t = h2*dinv
__device__ float  g_u   [WTOT];   // layer2 window accumulator (unnormalized)

// ---------------------------------------------------------------------------
typedef unsigned long long ull;

__device__ __forceinline__ ull fma2(ull a, ull b, ull c) {
    ull d;
    asm("fma.rn.f32x2 %0, %1, %2, %3;" : "=l"(d) : "l"(a), "l"(b), "l"(c));
    return d;
}
__device__ __forceinline__ ull add2(ull a, ull b) {
    ull d;
    asm("add.rn.f32x2 %0, %1, %2;" : "=l"(d) : "l"(a), "l"(b));
    return d;
}
__device__ __forceinline__ ull pack2(float lo, float hi) {
    ull d;
    asm("mov.b64 %0, {%1, %2};" : "=l"(d) : "f"(lo), "f"(hi));
    return d;
}
__device__ __forceinline__ void unpack2(ull v, float& lo, float& hi) {
    asm("mov.b64 {%0, %1}, %2;" : "=f"(lo), "=f"(hi) : "l"(v));
}
__device__ __forceinline__ void red4(float4* p, float a, float b, float c) {
    size_t q = __cvta_generic_to_global(p);
    asm volatile("red.global.add.v4.f32 [%0], {%1, %2, %3, %4};"
                 :: "l"(q), "f"(a), "f"(b), "f"(c), "f"(0.0f) : "memory");
}

// ---------------------------------------------------------------------------
// K2 (fused): blocks [0, DEG_B): degree histogram (deg zero at entry; +1 self
// loop applied in k_node); blocks [DEG_B, ...): raw h = x@W1.
#define DEG_B 384
__global__ __launch_bounds__(256)
void k_fused(const longlong2* __restrict__ Xll,
             const float* __restrict__ W1,
             const int* __restrict__ dst, int N, int E) {
    if (blockIdx.x < DEG_B) {
        int stride = DEG_B * blockDim.x;
        int i = blockIdx.x * blockDim.x + threadIdx.x;
        int E4 = E >> 2;
        const int4* dst4 = (const int4*)dst;
        for (int e = i; e < E4; e += stride) {
            int4 d = dst4[e];
            atomicAdd(&g_deg[d.x], 1.0f);
            atomicAdd(&g_deg[d.y], 1.0f);
            atomicAdd(&g_deg[d.z], 1.0f);
            atomicAdd(&g_deg[d.w], 1.0f);
        }
        for (int e = (E4 << 2) + i; e < E; e += stride)
            atomicAdd(&g_deg[dst[e]], 1.0f);
        return;
    }
    // linear path: 16 lanes per node, 4 nodes per warp iteration
    int lane = threadIdx.x & 31;
    int sub  = lane & 15;
    int half = lane >> 4;
    int warp = (((blockIdx.x - DEG_B) * blockDim.x) + threadIdx.x) >> 5;
    int nwarps = ((gridDim.x - DEG_B) * blockDim.x) >> 5;

    ull wp[4][3][2];
#pragma unroll
    for (int j = 0; j < 4; j++) {
        int c = sub + 16 * j;
#pragma unroll
        for (int k = 0; k < 3; k++) {
            wp[j][k][0] = pack2(__ldg(&W1[(4 * c + 0) * 3 + k]),
                                __ldg(&W1[(4 * c + 1) * 3 + k]));
            wp[j][k][1] = pack2(__ldg(&W1[(4 * c + 2) * 3 + k]),
                                __ldg(&W1[(4 * c + 3) * 3 + k]));
        }
    }

    int NG = N >> 2;
    for (int g = warp; g < NG; g += nwarps) {
        int nA = 4 * g + half;
        int nB = nA + 2;
        longlong2 va[4], vb[4];
        size_t baseA = (size_t)nA * 64 + sub;
        size_t baseB = (size_t)nB * 64 + sub;
#pragma unroll
        for (int j = 0; j < 4; j++) va[j] = Xll[baseA + 16 * j];
#pragma unroll
        for (int j = 0; j < 4; j++) vb[j] = Xll[baseB + 16 * j];

        ull aA0 = 0, aA1 = 0, aA2 = 0, aB0 = 0, aB1 = 0, aB2 = 0;
#pragma unroll
        for (int j = 0; j < 4; j++) {
            ull alo = (ull)va[j].x, ahi = (ull)va[j].y;
            ull blo = (ull)vb[j].x, bhi = (ull)vb[j].y;
            aA0 = fma2(alo, wp[j][0][0], aA0);  aA0 = fma2(ahi, wp[j][0][1], aA0);
            aA1 = fma2(alo, wp[j][1][0], aA1);  aA1 = fma2(ahi, wp[j][1][1], aA1);
            aA2 = fma2(alo, wp[j][2][0], aA2);  aA2 = fma2(ahi, wp[j][2][1], aA2);
            aB0 = fma2(blo, wp[j][0][0], aB0);  aB0 = fma2(bhi, wp[j][0][1], aB0);
            aB1 = fma2(blo, wp[j][1][0], aB1);  aB1 = fma2(bhi, wp[j][1][1], aB1);
            aB2 = fma2(blo, wp[j][2][0], aB2);  aB2 = fma2(bhi, wp[j][2][1], aB2);
        }
        float t0, t1;
        unpack2(aA0, t0, t1); float hA0 = t0 + t1;
        unpack2(aA1, t0, t1); float hA1 = t0 + t1;
        unpack2(aA2, t0, t1); float hA2 = t0 + t1;
        unpack2(aB0, t0, t1); float hB0 = t0 + t1;
        unpack2(aB1, t0, t1); float hB1 = t0 + t1;
        unpack2(aB2, t0, t1); float hB2 = t0 + t1;
        ull pA = pack2(hA0, hA1);
        ull pB = pack2(hB0, hB1);
#pragma unroll
        for (int off = 8; off; off >>= 1) {
            ull qA = __shfl_xor_sync(0xffffffffu, pA, off);
            ull qB = __shfl_xor_sync(0xffffffffu, pB, off);
            float rA = __shfl_xor_sync(0xffffffffu, hA2, off);
            float rB = __shfl_xor_sync(0xffffffffu, hB2, off);
            pA = add2(pA, qA);
            pB = add2(pB, qB);
            hA2 += rA;
            hB2 += rB;
        }
        if (sub == 0) {
            float x0, x1;
            unpack2(pA, x0, x1);
            g_hs[nA] = make_float4(x0, x1, hA2, 0.0f);
            unpack2(pB, x0, x1);
            g_hs[nB] = make_float4(x0, x1, hB2, 0.0f);
        }
    }
}

// K3: node pass — dinv = rsqrt(deg+1); hs = h*dinv; agg1 = hs (self loop)
__global__ void k_node(int N) {
    cudaGridDependencySynchronize();
    int n = blockIdx.x * blockDim.x + threadIdx.x;
    if (n >= N) return;
    float dv = rsqrtf(g_deg[n] + 1.0f);
    g_dinv[n] = dv;
    float4 h = g_hs[n];
    float4 hs = make_float4(h.x * dv, h.y * dv, h.z * dv, 0.0f);
    g_hs[n] = hs;
    g_agg1[n] = hs;
}

// K4: layer-1 scatter: agg1[d] += hs[s]   (4 edges/thread)
__global__ __launch_bounds__(256)
void k_edge1(const int* __restrict__ ei, int E) {
    cudaGridDependencySynchronize();
    int stride = gridDim.x * blockDim.x;
    int i = blockIdx.x * blockDim.x + threadIdx.x;
    int E4 = E >> 2;
    const int4* s4 = (const int4*)ei;
    const int4* d4 = (const int4*)(ei + E);
    for (int e = i; e < E4; e += stride) {
        int4 s = s4[e];
        int4 d = d4[e];
        float4 h0 = g_hs[s.x];
        float4 h1 = g_hs[s.y];
        float4 h2 = g_hs[s.z];
        float4 h3 = g_hs[s.w];
        red4(&g_agg1[d.x], h0.x, h0.y, h0.z);
        red4(&g_agg1[d.y], h1.x, h1.y, h1.z);
        red4(&g_agg1[d.z], h2.x, h2.y, h2.z);
        red4(&g_agg1[d.w], h3.x, h3.y, h3.z);
    }
    for (int e = (E4 << 2) + i; e < E; e += stride) {
        int s = ei[e], d = ei[E + e];
        float4 h = g_hs[s];
        red4(&g_agg1[d], h.x, h.y, h.z);
    }
}

// K5: finalize layer1: a = agg1*dinv (+b1, relu) -> h2 -> t = h2*dinv.
//     Seed window accumulator g_u with self-loop term t[n] (overwrite).
__global__ void k_final1(const float* __restrict__ b1,
                         const float* __restrict__ W2, int N) {
    cudaGridDependencySynchronize();
    int n = blockIdx.x * blockDim.x + threadIdx.x;
    if (n >= N) return;
    float dv = g_dinv[n];
    float4 a = g_agg1[n];
    float o0 = fmaxf(a.x * dv + __ldg(&b1[0]), 0.0f);
    float o1 = fmaxf(a.y * dv + __ldg(&b1[1]), 0.0f);
    float o2 = fmaxf(a.z * dv + __ldg(&b1[2]), 0.0f);
    float h2 = o0 * __ldg(&W2[0]) + o1 * __ldg(&W2[1]) + o2 * __ldg(&W2[2]);
    float t = h2 * dv;
    g_t[n] = t;
    int r = n & (ILEN - 1);
    if (r < PLEN)
        g_u[(n >> 12) * PLEN + r] = t;
}

// K6: layer-2 scatter, filtered, unnormalized: u[d] += t[s].
// src int4 loaded only if at least one of its 4 edges survives the filter.
__global__ __launch_bounds__(256)
void k_edge2(const int* __restrict__ ei, int E) {
    cudaGridDependencySynchronize();
    int stride = gridDim.x * blockDim.x;
    int i = blockIdx.x * blockDim.x + threadIdx.x;
    int E4 = E >> 2;
    const int4* s4 = (const int4*)ei;
    const int4* d4 = (const int4*)(ei + E);
    for (int e = i; e < E4; e += stride) {
        int4 d = d4[e];
        int r0 = d.x & (ILEN - 1);
        int r1 = d.y & (ILEN - 1);
        int r2 = d.z & (ILEN - 1);
        int r3 = d.w & (ILEN - 1);
        if ((r0 < PLEN) | (r1 < PLEN) | (r2 < PLEN) | (r3 < PLEN)) {
            int4 s = s4[e];
            if (r0 < PLEN) atomicAdd(&g_u[(d.x >> 12) * PLEN + r0], g_t[s.x]);
            if (r1 < PLEN) atomicAdd(&g_u[(d.y >> 12) * PLEN + r1], g_t[s.y]);
            if (r2 < PLEN) atomicAdd(&g_u[(d.z >> 12) * PLEN + r2], g_t[s.z]);
            if (r3 < PLEN) atomicAdd(&g_u[(d.w >> 12) * PLEN + r3], g_t[s.w]);
        }
    }
    for (int e = (E4 << 2) + i; e < E; e += stride) {
        int d = ei[E + e];
        int r = d & (ILEN - 1);
        if (r < PLEN)
            atomicAdd(&g_u[(d >> 12) * PLEN + r], g_t[ei[e]]);
    }
}

// K7: final output: out = u * dinv[node] + b2.  Also re-zeroes g_deg to
// restore the entry invariant for the next execution/graph replay.
__global__ void k_out(const float* __restrict__ b2, float* __restrict__ out,
                      int N) {
    cudaGridDependencySynchronize();
    int i = blockIdx.x * blockDim.x + threadIdx.x;
    if (i < N) g_deg[i] = 0.0f;
    if (i >= WTOT) return;
    int n = (i >> 10) * ILEN + (i & (PLEN - 1));
    out[i] = g_u[i] * g_dinv[n] + __ldg(&b2[0]);
}

// ---------------------------------------------------------------------------
static void launch_pdl(const void* fn, dim3 grid, dim3 block, void** args) {
    cudaLaunchConfig_t cfg = {};
    cfg.gridDim  = grid;
    cfg.blockDim = block;
    cfg.stream   = 0;
    cudaLaunchAttribute attr[1];
    attr[0].id = cudaLaunchAttributeProgrammaticStreamSerialization;
    attr[0].val.programmaticStreamSerializationAllowed = 1;
    cfg.attrs = attr;
    cfg.numAttrs = 1;
    cudaLaunchKernelExC(&cfg, fn, args);
}

extern "C" void kernel_launch(void* const* d_in, const int* in_sizes, int n_in,
                              void* d_out, int out_size) {
    const float* X   = (const float*)d_in[0];   // [N,256]
    const float* W1  = (const float*)d_in[1];   // [256,3]
    const float* b1  = (const float*)d_in[2];   // [3]
    const float* W2  = (const float*)d_in[3];   // [3,1]
    const float* b2  = (const float*)d_in[4];   // [1]
    const int*   ei  = (const int*)d_in[5];     // [2,E]
    float*       out = (float*)d_out;

    int N = in_sizes[0] / 256;
    int E = in_sizes[5] / 2;

    const int T = 256;
    int nb_node = (N + T - 1) / T;

    const int* dstp = ei + E;
    {   // k_fused (g_deg already zero: .bss init / re-zeroed by k_out)
        k_fused<<<DEG_B + 768, T>>>((const longlong2*)X, W1, dstp, N, E);
    }
    {   // k_node
        void* args[] = { &N };
        launch_pdl((const void*)k_node, dim3(nb_node), dim3(T), args);
    }
    {   // k_edge1
        void* args[] = { (void*)&ei, &E };
        launch_pdl((const void*)k_edge1, dim3(4096), dim3(T), args);
    }
    {   // k_final1
        void* args[] = { (void*)&b1, (void*)&W2, &N };
        launch_pdl((const void*)k_final1, dim3(nb_node), dim3(T), args);
    }
    {   // k_edge2
        void* args[] = { (void*)&ei, &E };
        launch_pdl((const void*)k_edge2, dim3(4096), dim3(T), args);
    }
    {   // k_out (covers N threads: zeroes g_deg, writes WTOT outputs)
        void* args[] = { (void*)&b2, (void*)&out, &N };
        launch_pdl((const void*)k_out, dim3(nb_node), dim3(T), args);
    }
}

// round 14
// speedup vs baseline: 1.2639x; 1.1267x over previous
#include <cuda_runtime.h>
#include <cuda_bf16.h>
#include <cstdint>

#define NMAX   131072      // B*INPUT_LEN
#define ILEN   4096
#define PLEN   1024
#define WTOT   (NMAX / ILEN * PLEN)   // 32768 output elements

// Scratch (__device__ globals; allocation forbidden).
// INVARIANT: g_deg is all-zero at kernel_launch entry. It is zero at module
// load (.bss), and k_out re-zeroes it at the end of every execution.
__device__ float  g_deg [NMAX];
__device__ float  g_dinv[NMAX];
__device__ float4 g_hs  [NMAX];   // raw h = x@W1, then h*dinv after k_node
__device__ float4 g_agg1[NMAX];   // layer1 unnormalized aggregator
__device__ float  g_t   [NMAX];   // layer2 pre-scaled messages t = h2*dinv
__device__ float  g_u   [WTOT];   // layer2 window accumulator (unnormalized)

// ---------------------------------------------------------------------------
typedef unsigned long long ull;

__device__ __forceinline__ ull fma2(ull a, ull b, ull c) {
    ull d;
    asm("fma.rn.f32x2 %0, %1, %2, %3;" : "=l"(d) : "l"(a), "l"(b), "l"(c));
    return d;
}
__device__ __forceinline__ ull add2(ull a, ull b) {
    ull d;
    asm("add.rn.f32x2 %0, %1, %2;" : "=l"(d) : "l"(a), "l"(b));
    return d;
}
__device__ __forceinline__ ull pack2(float lo, float hi) {
    ull d;
    asm("mov.b64 %0, {%1, %2};" : "=l"(d) : "f"(lo), "f"(hi));
    return d;
}
__device__ __forceinline__ void unpack2(ull v, float& lo, float& hi) {
    asm("mov.b64 {%0, %1}, %2;" : "=f"(lo), "=f"(hi) : "l"(v));
}
__device__ __forceinline__ void red4(float4* p, float a, float b, float c) {
    size_t q = __cvta_generic_to_global(p);
    asm volatile("red.global.add.v4.f32 [%0], {%1, %2, %3, %4};"
                 :: "l"(q), "f"(a), "f"(b), "f"(c), "f"(0.0f) : "memory");
}

// ---------------------------------------------------------------------------
// K2 (fused): blocks [0, DEG_B): degree histogram; rest: raw h = x@W1 with
// software-pipelined (double-buffered) X loads.
#define DEG_B 384
__global__ __launch_bounds__(256)
void k_fused(const longlong2* __restrict__ Xll,
             const float* __restrict__ W1,
             const int* __restrict__ dst, int N, int E) {
    if (blockIdx.x < DEG_B) {
        int stride = DEG_B * blockDim.x;
        int i = blockIdx.x * blockDim.x + threadIdx.x;
        int E4 = E >> 2;
        const int4* dst4 = (const int4*)dst;
        for (int e = i; e < E4; e += stride) {
            int4 d = dst4[e];
            atomicAdd(&g_deg[d.x], 1.0f);
            atomicAdd(&g_deg[d.y], 1.0f);
            atomicAdd(&g_deg[d.z], 1.0f);
            atomicAdd(&g_deg[d.w], 1.0f);
        }
        for (int e = (E4 << 2) + i; e < E; e += stride)
            atomicAdd(&g_deg[dst[e]], 1.0f);
        return;
    }
    // linear path: 16 lanes per node, 4 nodes per warp iteration, prefetched
    int lane = threadIdx.x & 31;
    int sub  = lane & 15;
    int half = lane >> 4;
    int warp = (((blockIdx.x - DEG_B) * blockDim.x) + threadIdx.x) >> 5;
    int nwarps = ((gridDim.x - DEG_B) * blockDim.x) >> 5;

    ull wp[4][3][2];
#pragma unroll
    for (int j = 0; j < 4; j++) {
        int c = sub + 16 * j;
#pragma unroll
        for (int k = 0; k < 3; k++) {
            wp[j][k][0] = pack2(__ldg(&W1[(4 * c + 0) * 3 + k]),
                                __ldg(&W1[(4 * c + 1) * 3 + k]));
            wp[j][k][1] = pack2(__ldg(&W1[(4 * c + 2) * 3 + k]),
                                __ldg(&W1[(4 * c + 3) * 3 + k]));
        }
    }

    int NG = N >> 2;
    int g = warp;
    longlong2 va[4], vb[4];
    if (g < NG) {
        size_t baseA = (size_t)(4 * g + half) * 64 + sub;
#pragma unroll
        for (int j = 0; j < 4; j++) va[j] = Xll[baseA + 16 * j];
#pragma unroll
        for (int j = 0; j < 4; j++) vb[j] = Xll[baseA + 128 + 16 * j];
    }
    while (g < NG) {
        int gn = g + nwarps;
        // ---- prefetch next group's 8 loads (independent of compute) ----
        longlong2 na[4], nb[4];
        if (gn < NG) {
            size_t baseN = (size_t)(4 * gn + half) * 64 + sub;
#pragma unroll
            for (int j = 0; j < 4; j++) na[j] = Xll[baseN + 16 * j];
#pragma unroll
            for (int j = 0; j < 4; j++) nb[j] = Xll[baseN + 128 + 16 * j];
        }
        // ---- compute current group ----
        int nA = 4 * g + half;
        int nB = nA + 2;
        ull aA0 = 0, aA1 = 0, aA2 = 0, aB0 = 0, aB1 = 0, aB2 = 0;
#pragma unroll
        for (int j = 0; j < 4; j++) {
            ull alo = (ull)va[j].x, ahi = (ull)va[j].y;
            ull blo = (ull)vb[j].x, bhi = (ull)vb[j].y;
            aA0 = fma2(alo, wp[j][0][0], aA0);  aA0 = fma2(ahi, wp[j][0][1], aA0);
            aA1 = fma2(alo, wp[j][1][0], aA1);  aA1 = fma2(ahi, wp[j][1][1], aA1);
            aA2 = fma2(alo, wp[j][2][0], aA2);  aA2 = fma2(ahi, wp[j][2][1], aA2);
            aB0 = fma2(blo, wp[j][0][0], aB0);  aB0 = fma2(bhi, wp[j][0][1], aB0);
            aB1 = fma2(blo, wp[j][1][0], aB1);  aB1 = fma2(bhi, wp[j][1][1], aB1);
            aB2 = fma2(blo, wp[j][2][0], aB2);  aB2 = fma2(bhi, wp[j][2][1], aB2);
        }
        float t0, t1;
        unpack2(aA0, t0, t1); float hA0 = t0 + t1;
        unpack2(aA1, t0, t1); float hA1 = t0 + t1;
        unpack2(aA2, t0, t1); float hA2 = t0 + t1;
        unpack2(aB0, t0, t1); float hB0 = t0 + t1;
        unpack2(aB1, t0, t1); float hB1 = t0 + t1;
        unpack2(aB2, t0, t1); float hB2 = t0 + t1;
        ull pA = pack2(hA0, hA1);
        ull pB = pack2(hB0, hB1);
#pragma unroll
        for (int off = 8; off; off >>= 1) {
            ull qA = __shfl_xor_sync(0xffffffffu, pA, off);
            ull qB = __shfl_xor_sync(0xffffffffu, pB, off);
            float rA = __shfl_xor_sync(0xffffffffu, hA2, off);
            float rB = __shfl_xor_sync(0xffffffffu, hB2, off);
            pA = add2(pA, qA);
            pB = add2(pB, qB);
            hA2 += rA;
            hB2 += rB;
        }
        if (sub == 0) {
            float x0, x1;
            unpack2(pA, x0, x1);
            g_hs[nA] = make_float4(x0, x1, hA2, 0.0f);
            unpack2(pB, x0, x1);
            g_hs[nB] = make_float4(x0, x1, hB2, 0.0f);
        }
        // ---- rotate buffers ----
#pragma unroll
        for (int j = 0; j < 4; j++) { va[j] = na[j]; vb[j] = nb[j]; }
        g = gn;
    }
}

// K3: node pass — dinv = rsqrt(deg+1); hs = h*dinv; agg1 = hs (self loop)
__global__ void k_node(int N) {
    cudaGridDependencySynchronize();
    int n = blockIdx.x * blockDim.x + threadIdx.x;
    if (n >= N) return;
    float dv = rsqrtf(g_deg[n] + 1.0f);
    g_dinv[n] = dv;
    float4 h = g_hs[n];
    float4 hs = make_float4(h.x * dv, h.y * dv, h.z * dv, 0.0f);
    g_hs[n] = hs;
    g_agg1[n] = hs;
}

// K4: layer-1 scatter: agg1[d] += hs[s]   (4 edges/thread)
__global__ __launch_bounds__(256)
void k_edge1(const int* __restrict__ ei, int E) {
    cudaGridDependencySynchronize();
    int stride = gridDim.x * blockDim.x;
    int i = blockIdx.x * blockDim.x + threadIdx.x;
    int E4 = E >> 2;
    const int4* s4 = (const int4*)ei;
    const int4* d4 = (const int4*)(ei + E);
    for (int e = i; e < E4; e += stride) {
        int4 s = s4[e];
        int4 d = d4[e];
        float4 h0 = g_hs[s.x];
        float4 h1 = g_hs[s.y];
        float4 h2 = g_hs[s.z];
        float4 h3 = g_hs[s.w];
        red4(&g_agg1[d.x], h0.x, h0.y, h0.z);
        red4(&g_agg1[d.y], h1.x, h1.y, h1.z);
        red4(&g_agg1[d.z], h2.x, h2.y, h2.z);
        red4(&g_agg1[d.w], h3.x, h3.y, h3.z);
    }
    for (int e = (E4 << 2) + i; e < E; e += stride) {
        int s = ei[e], d = ei[E + e];
        float4 h = g_hs[s];
        red4(&g_agg1[d], h.x, h.y, h.z);
    }
}

// K5: finalize layer1: a = agg1*dinv (+b1, relu) -> h2 -> t = h2*dinv.
//     Seed window accumulator g_u with self-loop term t[n] (overwrite).
__global__ void k_final1(const float* __restrict__ b1,
                         const float* __restrict__ W2, int N) {
    cudaGridDependencySynchronize();
    int n = blockIdx.x * blockDim.x + threadIdx.x;
    if (n >= N) return;
    float dv = g_dinv[n];
    float4 a = g_agg1[n];
    float o0 = fmaxf(a.x * dv + __ldg(&b1[0]), 0.0f);
    float o1 = fmaxf(a.y * dv + __ldg(&b1[1]), 0.0f);
    float o2 = fmaxf(a.z * dv + __ldg(&b1[2]), 0.0f);
    float h2 = o0 * __ldg(&W2[0]) + o1 * __ldg(&W2[1]) + o2 * __ldg(&W2[2]);
    float t = h2 * dv;
    g_t[n] = t;
    int r = n & (ILEN - 1);
    if (r < PLEN)
        g_u[(n >> 12) * PLEN + r] = t;
}

// K6: layer-2 scatter, filtered, unnormalized: u[d] += t[s].
__global__ __launch_bounds__(256)
void k_edge2(const int* __restrict__ ei, int E) {
    cudaGridDependencySynchronize();
    int stride = gridDim.x * blockDim.x;
    int i = blockIdx.x * blockDim.x + threadIdx.x;
    int E4 = E >> 2;
    const int4* s4 = (const int4*)ei;
    const int4* d4 = (const int4*)(ei + E);
    for (int e = i; e < E4; e += stride) {
        int4 d = d4[e];
        int r0 = d.x & (ILEN - 1);
        int r1 = d.y & (ILEN - 1);
        int r2 = d.z & (ILEN - 1);
        int r3 = d.w & (ILEN - 1);
        if ((r0 < PLEN) | (r1 < PLEN) | (r2 < PLEN) | (r3 < PLEN)) {
            int4 s = s4[e];
            if (r0 < PLEN) atomicAdd(&g_u[(d.x >> 12) * PLEN + r0], g_t[s.x]);
            if (r1 < PLEN) atomicAdd(&g_u[(d.y >> 12) * PLEN + r1], g_t[s.y]);
            if (r2 < PLEN) atomicAdd(&g_u[(d.z >> 12) * PLEN + r2], g_t[s.z]);
            if (r3 < PLEN) atomicAdd(&g_u[(d.w >> 12) * PLEN + r3], g_t[s.w]);
        }
    }
    for (int e = (E4 << 2) + i; e < E; e += stride) {
        int d = ei[E + e];
        int r = d & (ILEN - 1);
        if (r < PLEN)
            atomicAdd(&g_u[(d >> 12) * PLEN + r], g_t[ei[e]]);
    }
}

// K7: final output: out = u * dinv[node] + b2.  Also re-zeroes g_deg.
__global__ void k_out(const float* __restrict__ b2, float* __restrict__ out,
                      int N) {
    cudaGridDependencySynchronize();
    int i = blockIdx.x * blockDim.x + threadIdx.x;
    if (i < N) g_deg[i] = 0.0f;
    if (i >= WTOT) return;
    int n = (i >> 10) * ILEN + (i & (PLEN - 1));
    out[i] = g_u[i] * g_dinv[n] + __ldg(&b2[0]);
}

// ---------------------------------------------------------------------------
static void launch_pdl(const void* fn, dim3 grid, dim3 block, void** args) {
    cudaLaunchConfig_t cfg = {};
    cfg.gridDim  = grid;
    cfg.blockDim = block;
    cfg.stream   = 0;
    cudaLaunchAttribute attr[1];
    attr[0].id = cudaLaunchAttributeProgrammaticStreamSerialization;
    attr[0].val.programmaticStreamSerializationAllowed = 1;
    cfg.attrs = attr;
    cfg.numAttrs = 1;
    cudaLaunchKernelExC(&cfg, fn, args);
}

extern "C" void kernel_launch(void* const* d_in, const int* in_sizes, int n_in,
                              void* d_out, int out_size) {
    const float* X   = (const float*)d_in[0];   // [N,256]
    const float* W1  = (const float*)d_in[1];   // [256,3]
    const float* b1  = (const float*)d_in[2];   // [3]
    const float* W2  = (const float*)d_in[3];   // [3,1]
    const float* b2  = (const float*)d_in[4];   // [1]
    const int*   ei  = (const int*)d_in[5];     // [2,E]
    float*       out = (float*)d_out;

    int N = in_sizes[0] / 256;
    int E = in_sizes[5] / 2;

    const int T = 256;
    int nb_node = (N + T - 1) / T;

    const int* dstp = ei + E;
    {   // k_fused (g_deg already zero: .bss init / re-zeroed by k_out)
        k_fused<<<DEG_B + 768, T>>>((const longlong2*)X, W1, dstp, N, E);
    }
    {   // k_node
        void* args[] = { &N };
        launch_pdl((const void*)k_node, dim3(nb_node), dim3(T), args);
    }
    {   // k_edge1
        void* args[] = { (void*)&ei, &E };
        launch_pdl((const void*)k_edge1, dim3(4096), dim3(T), args);
    }
    {   // k_final1
        void* args[] = { (void*)&b1, (void*)&W2, &N };
        launch_pdl((const void*)k_final1, dim3(nb_node), dim3(T), args);
    }
    {   // k_edge2
        void* args[] = { (void*)&ei, &E };
        launch_pdl((const void*)k_edge2, dim3(4096), dim3(T), args);
    }
    {   // k_out (covers N threads: zeroes g_deg, writes WTOT outputs)
        void* args[] = { (void*)&b2, (void*)&out, &N };
        launch_pdl((const void*)k_out, dim3(nb_node), dim3(T), args);
    }
}

// round 15
// speedup vs baseline: 1.2673x; 1.0026x over previous
#include <cuda_runtime.h>
#include <cuda_bf16.h>
#include <cstdint>

#define NMAX   131072      // B*INPUT_LEN
#define ILEN   4096
#define PLEN   1024
#define WTOT   (NMAX / ILEN * PLEN)   // 32768 output elements

// Scratch (__device__ globals; allocation forbidden).
// INVARIANT: g_deg is all-zero at kernel_launch entry. It is zero at module
// load (.bss), and k_out re-zeroes it at the end of every execution.
__device__ float  g_deg [NMAX];
__device__ float  g_dinv[NMAX];
__device__ float4 g_hs  [NMAX];   // raw h = x@W1, then h*dinv after k_node
__device__ float4 g_agg1[NMAX];   // layer1 unnormalized aggregator
__device__ float  g_t   [NMAX];   // layer2 pre-scaled messages t = h2*dinv
__device__ float  g_u   [WTOT];   // layer2 window accumulator (unnormalized)

// ---------------------------------------------------------------------------
typedef unsigned long long ull;

__device__ __forceinline__ ull fma2(ull a, ull b, ull c) {
    ull d;
    asm("fma.rn.f32x2 %0, %1, %2, %3;" : "=l"(d) : "l"(a), "l"(b), "l"(c));
    return d;
}
__device__ __forceinline__ ull add2(ull a, ull b) {
    ull d;
    asm("add.rn.f32x2 %0, %1, %2;" : "=l"(d) : "l"(a), "l"(b));
    return d;
}
__device__ __forceinline__ ull pack2(float lo, float hi) {
    ull d;
    asm("mov.b64 %0, {%1, %2};" : "=l"(d) : "f"(lo), "f"(hi));
    return d;
}
__device__ __forceinline__ void unpack2(ull v, float& lo, float& hi) {
    asm("mov.b64 {%0, %1}, %2;" : "=f"(lo), "=f"(hi) : "l"(v));
}
__device__ __forceinline__ void red4(float4* p, float a, float b, float c) {
    size_t q = __cvta_generic_to_global(p);
    asm volatile("red.global.add.v4.f32 [%0], {%1, %2, %3, %4};"
                 :: "l"(q), "f"(a), "f"(b), "f"(c), "f"(0.0f) : "memory");
}
__device__ __forceinline__ void l2_prefetch(const void* p) {
    asm volatile("prefetch.global.L2 [%0];" :: "l"(p));
}

// ---------------------------------------------------------------------------
// K2 (fused): blocks [0, DEG_B): degree histogram; rest: raw h = x@W1 with
// depth-1 register pipeline + distance-2 L2 prefetch (1 line/lane/iter).
#define DEG_B 384
__global__ __launch_bounds__(256)
void k_fused(const longlong2* __restrict__ Xll,
             const float* __restrict__ W1,
             const int* __restrict__ dst, int N, int E) {
    if (blockIdx.x < DEG_B) {
        int stride = DEG_B * blockDim.x;
        int i = blockIdx.x * blockDim.x + threadIdx.x;
        int E4 = E >> 2;
        const int4* dst4 = (const int4*)dst;
        for (int e = i; e < E4; e += stride) {
            int4 d = dst4[e];
            atomicAdd(&g_deg[d.x], 1.0f);
            atomicAdd(&g_deg[d.y], 1.0f);
            atomicAdd(&g_deg[d.z], 1.0f);
            atomicAdd(&g_deg[d.w], 1.0f);
        }
        for (int e = (E4 << 2) + i; e < E; e += stride)
            atomicAdd(&g_deg[dst[e]], 1.0f);
        return;
    }
    // linear path: 16 lanes per node, 4 nodes per warp iteration, prefetched
    int lane = threadIdx.x & 31;
    int sub  = lane & 15;
    int half = lane >> 4;
    int warp = (((blockIdx.x - DEG_B) * blockDim.x) + threadIdx.x) >> 5;
    int nwarps = ((gridDim.x - DEG_B) * blockDim.x) >> 5;

    ull wp[4][3][2];
#pragma unroll
    for (int j = 0; j < 4; j++) {
        int c = sub + 16 * j;
#pragma unroll
        for (int k = 0; k < 3; k++) {
            wp[j][k][0] = pack2(__ldg(&W1[(4 * c + 0) * 3 + k]),
                                __ldg(&W1[(4 * c + 1) * 3 + k]));
            wp[j][k][1] = pack2(__ldg(&W1[(4 * c + 2) * 3 + k]),
                                __ldg(&W1[(4 * c + 3) * 3 + k]));
        }
    }

    int NG = N >> 2;
    int g = warp;
    longlong2 va[4], vb[4];
    if (g < NG) {
        size_t baseA = (size_t)(4 * g + half) * 64 + sub;
#pragma unroll
        for (int j = 0; j < 4; j++) va[j] = Xll[baseA + 16 * j];
#pragma unroll
        for (int j = 0; j < 4; j++) vb[j] = Xll[baseA + 128 + 16 * j];
        // L2 prefetch for the g+1 group (one 128B line per lane, 4KB/warp)
        int g1 = g + nwarps;
        if (g1 < NG)
            l2_prefetch((const char*)Xll + (size_t)(4 * g1) * 1024 + lane * 128);
    }
    while (g < NG) {
        int gn = g + nwarps;
        // ---- L2 prefetch distance 2 (no registers consumed) ----
        int g2 = gn + nwarps;
        if (g2 < NG)
            l2_prefetch((const char*)Xll + (size_t)(4 * g2) * 1024 + lane * 128);
        // ---- prefetch next group's 8 loads into registers ----
        longlong2 na[4], nb[4];
        if (gn < NG) {
            size_t baseN = (size_t)(4 * gn + half) * 64 + sub;
#pragma unroll
            for (int j = 0; j < 4; j++) na[j] = Xll[baseN + 16 * j];
#pragma unroll
            for (int j = 0; j < 4; j++) nb[j] = Xll[baseN + 128 + 16 * j];
        }
        // ---- compute current group ----
        int nA = 4 * g + half;
        int nB = nA + 2;
        ull aA0 = 0, aA1 = 0, aA2 = 0, aB0 = 0, aB1 = 0, aB2 = 0;
#pragma unroll
        for (int j = 0; j < 4; j++) {
            ull alo = (ull)va[j].x, ahi = (ull)va[j].y;
            ull blo = (ull)vb[j].x, bhi = (ull)vb[j].y;
            aA0 = fma2(alo, wp[j][0][0], aA0);  aA0 = fma2(ahi, wp[j][0][1], aA0);
            aA1 = fma2(alo, wp[j][1][0], aA1);  aA1 = fma2(ahi, wp[j][1][1], aA1);
            aA2 = fma2(alo, wp[j][2][0], aA2);  aA2 = fma2(ahi, wp[j][2][1], aA2);
            aB0 = fma2(blo, wp[j][0][0], aB0);  aB0 = fma2(bhi, wp[j][0][1], aB0);
            aB1 = fma2(blo, wp[j][1][0], aB1);  aB1 = fma2(bhi, wp[j][1][1], aB1);
            aB2 = fma2(blo, wp[j][2][0], aB2);  aB2 = fma2(bhi, wp[j][2][1], aB2);
        }
        float t0, t1;
        unpack2(aA0, t0, t1); float hA0 = t0 + t1;
        unpack2(aA1, t0, t1); float hA1 = t0 + t1;
        unpack2(aA2, t0, t1); float hA2 = t0 + t1;
        unpack2(aB0, t0, t1); float hB0 = t0 + t1;
        unpack2(aB1, t0, t1); float hB1 = t0 + t1;
        unpack2(aB2, t0, t1); float hB2 = t0 + t1;
        ull pA = pack2(hA0, hA1);
        ull pB = pack2(hB0, hB1);
#pragma unroll
        for (int off = 8; off; off >>= 1) {
            ull qA = __shfl_xor_sync(0xffffffffu, pA, off);
            ull qB = __shfl_xor_sync(0xffffffffu, pB, off);
            float rA = __shfl_xor_sync(0xffffffffu, hA2, off);
            float rB = __shfl_xor_sync(0xffffffffu, hB2, off);
            pA = add2(pA, qA);
            pB = add2(pB, qB);
            hA2 += rA;
            hB2 += rB;
        }
        if (sub == 0) {
            float x0, x1;
            unpack2(pA, x0, x1);
            g_hs[nA] = make_float4(x0, x1, hA2, 0.0f);
            unpack2(pB, x0, x1);
            g_hs[nB] = make_float4(x0, x1, hB2, 0.0f);
        }
        // ---- rotate buffers ----
#pragma unroll
        for (int j = 0; j < 4; j++) { va[j] = na[j]; vb[j] = nb[j]; }
        g = gn;
    }
}

// K3: node pass — dinv = rsqrt(deg+1); hs = h*dinv; agg1 = hs (self loop)
__global__ void k_node(int N) {
    cudaGridDependencySynchronize();
    int n = blockIdx.x * blockDim.x + threadIdx.x;
    if (n >= N) return;
    float dv = rsqrtf(g_deg[n] + 1.0f);
    g_dinv[n] = dv;
    float4 h = g_hs[n];
    float4 hs = make_float4(h.x * dv, h.y * dv, h.z * dv, 0.0f);
    g_hs[n] = hs;
    g_agg1[n] = hs;
}

// K4: layer-1 scatter: agg1[d] += hs[s]   (4 edges/thread)
__global__ __launch_bounds__(256)
void k_edge1(const int* __restrict__ ei, int E) {
    cudaGridDependencySynchronize();
    int stride = gridDim.x * blockDim.x;
    int i = blockIdx.x * blockDim.x + threadIdx.x;
    int E4 = E >> 2;
    const int4* s4 = (const int4*)ei;
    const int4* d4 = (const int4*)(ei + E);
    for (int e = i; e < E4; e += stride) {
        int4 s = s4[e];
        int4 d = d4[e];
        float4 h0 = g_hs[s.x];
        float4 h1 = g_hs[s.y];
        float4 h2 = g_hs[s.z];
        float4 h3 = g_hs[s.w];
        red4(&g_agg1[d.x], h0.x, h0.y, h0.z);
        red4(&g_agg1[d.y], h1.x, h1.y, h1.z);
        red4(&g_agg1[d.z], h2.x, h2.y, h2.z);
        red4(&g_agg1[d.w], h3.x, h3.y, h3.z);
    }
    for (int e = (E4 << 2) + i; e < E; e += stride) {
        int s = ei[e], d = ei[E + e];
        float4 h = g_hs[s];
        red4(&g_agg1[d], h.x, h.y, h.z);
    }
}

// K5: finalize layer1: a = agg1*dinv (+b1, relu) -> h2 -> t = h2*dinv.
//     Seed window accumulator g_u with self-loop term t[n] (overwrite).
__global__ void k_final1(const float* __restrict__ b1,
                         const float* __restrict__ W2, int N) {
    cudaGridDependencySynchronize();
    int n = blockIdx.x * blockDim.x + threadIdx.x;
    if (n >= N) return;
    float dv = g_dinv[n];
    float4 a = g_agg1[n];
    float o0 = fmaxf(a.x * dv + __ldg(&b1[0]), 0.0f);
    float o1 = fmaxf(a.y * dv + __ldg(&b1[1]), 0.0f);
    float o2 = fmaxf(a.z * dv + __ldg(&b1[2]), 0.0f);
    float h2 = o0 * __ldg(&W2[0]) + o1 * __ldg(&W2[1]) + o2 * __ldg(&W2[2]);
    float t = h2 * dv;
    g_t[n] = t;
    int r = n & (ILEN - 1);
    if (r < PLEN)
        g_u[(n >> 12) * PLEN + r] = t;
}

// K6: layer-2 scatter, filtered, unnormalized: u[d] += t[s].
__global__ __launch_bounds__(256)
void k_edge2(const int* __restrict__ ei, int E) {
    cudaGridDependencySynchronize();
    int stride = gridDim.x * blockDim.x;
    int i = blockIdx.x * blockDim.x + threadIdx.x;
    int E4 = E >> 2;
    const int4* s4 = (const int4*)ei;
    const int4* d4 = (const int4*)(ei + E);
    for (int e = i; e < E4; e += stride) {
        int4 d = d4[e];
        int r0 = d.x & (ILEN - 1);
        int r1 = d.y & (ILEN - 1);
        int r2 = d.z & (ILEN - 1);
        int r3 = d.w & (ILEN - 1);
        if ((r0 < PLEN) | (r1 < PLEN) | (r2 < PLEN) | (r3 < PLEN)) {
            int4 s = s4[e];
            if (r0 < PLEN) atomicAdd(&g_u[(d.x >> 12) * PLEN + r0], g_t[s.x]);
            if (r1 < PLEN) atomicAdd(&g_u[(d.y >> 12) * PLEN + r1], g_t[s.y]);
            if (r2 < PLEN) atomicAdd(&g_u[(d.z >> 12) * PLEN + r2], g_t[s.z]);
            if (r3 < PLEN) atomicAdd(&g_u[(d.w >> 12) * PLEN + r3], g_t[s.w]);
        }
    }
    for (int e = (E4 << 2) + i; e < E; e += stride) {
        int d = ei[E + e];
        int r = d & (ILEN - 1);
        if (r < PLEN)
            atomicAdd(&g_u[(d >> 12) * PLEN + r], g_t[ei[e]]);
    }
}

// K7: final output: out = u * dinv[node] + b2.  Also re-zeroes g_deg.
__global__ void k_out(const float* __restrict__ b2, float* __restrict__ out,
                      int N) {
    cudaGridDependencySynchronize();
    int i = blockIdx.x * blockDim.x + threadIdx.x;
    if (i < N) g_deg[i] = 0.0f;
    if (i >= WTOT) return;
    int n = (i >> 10) * ILEN + (i & (PLEN - 1));
    out[i] = g_u[i] * g_dinv[n] + __ldg(&b2[0]);
}

// ---------------------------------------------------------------------------
static void launch_pdl(const void* fn, dim3 grid, dim3 block, void** args) {
    cudaLaunchConfig_t cfg = {};
    cfg.gridDim  = grid;
    cfg.blockDim = block;
    cfg.stream   = 0;
    cudaLaunchAttribute attr[1];
    attr[0].id = cudaLaunchAttributeProgrammaticStreamSerialization;
    attr[0].val.programmaticStreamSerializationAllowed = 1;
    cfg.attrs = attr;
    cfg.numAttrs = 1;
    cudaLaunchKernelExC(&cfg, fn, args);
}

extern "C" void kernel_launch(void* const* d_in, const int* in_sizes, int n_in,
                              void* d_out, int out_size) {
    const float* X   = (const float*)d_in[0];   // [N,256]
    const float* W1  = (const float*)d_in[1];   // [256,3]
    const float* b1  = (const float*)d_in[2];   // [3]
    const float* W2  = (const float*)d_in[3];   // [3,1]
    const float* b2  = (const float*)d_in[4];   // [1]
    const int*   ei  = (const int*)d_in[5];     // [2,E]
    float*       out = (float*)d_out;

    int N = in_sizes[0] / 256;
    int E = in_sizes[5] / 2;

    const int T = 256;
    int nb_node = (N + T - 1) / T;

    const int* dstp = ei + E;
    {   // k_fused (g_deg already zero: .bss init / re-zeroed by k_out)
        k_fused<<<DEG_B + 768, T>>>((const longlong2*)X, W1, dstp, N, E);
    }
    {   // k_node
        void* args[] = { &N };
        launch_pdl((const void*)k_node, dim3(nb_node), dim3(T), args);
    }
    {   // k_edge1
        void* args[] = { (void*)&ei, &E };
        launch_pdl((const void*)k_edge1, dim3(4096), dim3(T), args);
    }
    {   // k_final1
        void* args[] = { (void*)&b1, (void*)&W2, &N };
        launch_pdl((const void*)k_final1, dim3(nb_node), dim3(T), args);
    }
    {   // k_edge2
        void* args[] = { (void*)&ei, &E };
        launch_pdl((const void*)k_edge2, dim3(4096), dim3(T), args);
    }
    {   // k_out (covers N threads: zeroes g_deg, writes WTOT outputs)
        void* args[] = { (void*)&b2, (void*)&out, &N };
        launch_pdl((const void*)k_out, dim3(nb_node), dim3(T), args);
    }
}

// round 16
// speedup vs baseline: 1.2728x; 1.0043x over previous
#include <cuda_runtime.h>
#include <cuda_bf16.h>
#include <cstdint>

#define NMAX   131072      // B*INPUT_LEN
#define ILEN   4096
#define PLEN   1024
#define WTOT   (NMAX / ILEN * PLEN)   // 32768 output elements

// Scratch (__device__ globals; allocation forbidden).
// INVARIANT: g_deg is all-zero at kernel_launch entry. It is zero at module
// load (.bss), and k_out re-zeroes it at the end of every execution.
__device__ float  g_deg [NMAX];
__device__ float  g_dinv[NMAX];
__device__ float4 g_hs  [NMAX];   // raw h = x@W1, then h*dinv after k_node
__device__ float4 g_agg1[NMAX];   // layer1 unnormalized aggregator
__device__ float  g_t   [NMAX];   // layer2 pre-scaled messages t = h2*dinv
__device__ float  g_u   [WTOT];   // layer2 window accumulator (unnormalized)

// ---------------------------------------------------------------------------
typedef unsigned long long ull;

__device__ __forceinline__ ull fma2(ull a, ull b, ull c) {
    ull d;
    asm("fma.rn.f32x2 %0, %1, %2, %3;" : "=l"(d) : "l"(a), "l"(b), "l"(c));
    return d;
}
__device__ __forceinline__ ull add2(ull a, ull b) {
    ull d;
    asm("add.rn.f32x2 %0, %1, %2;" : "=l"(d) : "l"(a), "l"(b));
    return d;
}
__device__ __forceinline__ ull pack2(float lo, float hi) {
    ull d;
    asm("mov.b64 %0, {%1, %2};" : "=l"(d) : "f"(lo), "f"(hi));
    return d;
}
__device__ __forceinline__ void unpack2(ull v, float& lo, float& hi) {
    asm("mov.b64 {%0, %1}, %2;" : "=f"(lo), "=f"(hi) : "l"(v));
}
__device__ __forceinline__ void red4(float4* p, float a, float b, float c) {
    size_t q = __cvta_generic_to_global(p);
    asm volatile("red.global.add.v4.f32 [%0], {%1, %2, %3, %4};"
                 :: "l"(q), "f"(a), "f"(b), "f"(c), "f"(0.0f) : "memory");
}
__device__ __forceinline__ void l2_prefetch(const void* p) {
    asm volatile("prefetch.global.L2 [%0];" :: "l"(p));
}

// ---------------------------------------------------------------------------
// K2 (fused): deg path on blockIdx%3==0 (interleaved across waves so every
// wave carries a 1/3 atomic-bound : 2/3 DRAM-bound mix); rest: raw h = x@W1
// with depth-1 register pipeline + distance-2 L2 prefetch.
#define GRID_FUSED 1152
__global__ __launch_bounds__(256)
void k_fused(const longlong2* __restrict__ Xll,
             const float* __restrict__ W1,
             const int* __restrict__ dst, int N, int E) {
    int nDeg = (gridDim.x + 2) / 3;            // 384 for 1152
    int nLin = gridDim.x - nDeg;               // 768
    if (blockIdx.x % 3 == 0) {
        // ---- degree path ----
        int degIdx = blockIdx.x / 3;
        int stride = nDeg * blockDim.x;
        int i = degIdx * blockDim.x + threadIdx.x;
        int E4 = E >> 2;
        const int4* dst4 = (const int4*)dst;
        for (int e = i; e < E4; e += stride) {
            int4 d = dst4[e];
            atomicAdd(&g_deg[d.x], 1.0f);
            atomicAdd(&g_deg[d.y], 1.0f);
            atomicAdd(&g_deg[d.z], 1.0f);
            atomicAdd(&g_deg[d.w], 1.0f);
        }
        for (int e = (E4 << 2) + i; e < E; e += stride)
            atomicAdd(&g_deg[dst[e]], 1.0f);
        return;
    }
    // ---- linear path: 16 lanes/node, 4 nodes/warp-iter, pipelined ----
    int linIdx = blockIdx.x - blockIdx.x / 3 - 1;   // rank among %3!=0 blocks
    int lane = threadIdx.x & 31;
    int sub  = lane & 15;
    int half = lane >> 4;
    int warp = ((linIdx * blockDim.x) + threadIdx.x) >> 5;
    int nwarps = (nLin * blockDim.x) >> 5;

    ull wp[4][3][2];
#pragma unroll
    for (int j = 0; j < 4; j++) {
        int c = sub + 16 * j;
#pragma unroll
        for (int k = 0; k < 3; k++) {
            wp[j][k][0] = pack2(__ldg(&W1[(4 * c + 0) * 3 + k]),
                                __ldg(&W1[(4 * c + 1) * 3 + k]));
            wp[j][k][1] = pack2(__ldg(&W1[(4 * c + 2) * 3 + k]),
                                __ldg(&W1[(4 * c + 3) * 3 + k]));
        }
    }

    int NG = N >> 2;
    int g = warp;
    longlong2 va[4], vb[4];
    if (g < NG) {
        size_t baseA = (size_t)(4 * g + half) * 64 + sub;
#pragma unroll
        for (int j = 0; j < 4; j++) va[j] = Xll[baseA + 16 * j];
#pragma unroll
        for (int j = 0; j < 4; j++) vb[j] = Xll[baseA + 128 + 16 * j];
        int g1 = g + nwarps;
        if (g1 < NG)
            l2_prefetch((const char*)Xll + (size_t)(4 * g1) * 1024 + lane * 128);
    }
    while (g < NG) {
        int gn = g + nwarps;
        // ---- L2 prefetch distance 2 (no registers consumed) ----
        int g2 = gn + nwarps;
        if (g2 < NG)
            l2_prefetch((const char*)Xll + (size_t)(4 * g2) * 1024 + lane * 128);
        // ---- prefetch next group's 8 loads into registers ----
        longlong2 na[4], nb[4];
        if (gn < NG) {
            size_t baseN = (size_t)(4 * gn + half) * 64 + sub;
#pragma unroll
            for (int j = 0; j < 4; j++) na[j] = Xll[baseN + 16 * j];
#pragma unroll
            for (int j = 0; j < 4; j++) nb[j] = Xll[baseN + 128 + 16 * j];
        }
        // ---- compute current group ----
        int nA = 4 * g + half;
        int nB = nA + 2;
        ull aA0 = 0, aA1 = 0, aA2 = 0, aB0 = 0, aB1 = 0, aB2 = 0;
#pragma unroll
        for (int j = 0; j < 4; j++) {
            ull alo = (ull)va[j].x, ahi = (ull)va[j].y;
            ull blo = (ull)vb[j].x, bhi = (ull)vb[j].y;
            aA0 = fma2(alo, wp[j][0][0], aA0);  aA0 = fma2(ahi, wp[j][0][1], aA0);
            aA1 = fma2(alo, wp[j][1][0], aA1);  aA1 = fma2(ahi, wp[j][1][1], aA1);
            aA2 = fma2(alo, wp[j][2][0], aA2);  aA2 = fma2(ahi, wp[j][2][1], aA2);
            aB0 = fma2(blo, wp[j][0][0], aB0);  aB0 = fma2(bhi, wp[j][0][1], aB0);
            aB1 = fma2(blo, wp[j][1][0], aB1);  aB1 = fma2(bhi, wp[j][1][1], aB1);
            aB2 = fma2(blo, wp[j][2][0], aB2);  aB2 = fma2(bhi, wp[j][2][1], aB2);
        }
        float t0, t1;
        unpack2(aA0, t0, t1); float hA0 = t0 + t1;
        unpack2(aA1, t0, t1); float hA1 = t0 + t1;
        unpack2(aA2, t0, t1); float hA2 = t0 + t1;
        unpack2(aB0, t0, t1); float hB0 = t0 + t1;
        unpack2(aB1, t0, t1); float hB1 = t0 + t1;
        unpack2(aB2, t0, t1); float hB2 = t0 + t1;
        ull pA = pack2(hA0, hA1);
        ull pB = pack2(hB0, hB1);
#pragma unroll
        for (int off = 8; off; off >>= 1) {
            ull qA = __shfl_xor_sync(0xffffffffu, pA, off);
            ull qB = __shfl_xor_sync(0xffffffffu, pB, off);
            float rA = __shfl_xor_sync(0xffffffffu, hA2, off);
            float rB = __shfl_xor_sync(0xffffffffu, hB2, off);
            pA = add2(pA, qA);
            pB = add2(pB, qB);
            hA2 += rA;
            hB2 += rB;
        }
        if (sub == 0) {
            float x0, x1;
            unpack2(pA, x0, x1);
            g_hs[nA] = make_float4(x0, x1, hA2, 0.0f);
            unpack2(pB, x0, x1);
            g_hs[nB] = make_float4(x0, x1, hB2, 0.0f);
        }
        // ---- rotate buffers ----
#pragma unroll
        for (int j = 0; j < 4; j++) { va[j] = na[j]; vb[j] = nb[j]; }
        g = gn;
    }
}

// K3: node pass — dinv = rsqrt(deg+1); hs = h*dinv; agg1 = hs (self loop)
__global__ void k_node(int N) {
    cudaGridDependencySynchronize();
    int n = blockIdx.x * blockDim.x + threadIdx.x;
    if (n >= N) return;
    float dv = rsqrtf(g_deg[n] + 1.0f);
    g_dinv[n] = dv;
    float4 h = g_hs[n];
    float4 hs = make_float4(h.x * dv, h.y * dv, h.z * dv, 0.0f);
    g_hs[n] = hs;
    g_agg1[n] = hs;
}

// K4: layer-1 scatter: agg1[d] += hs[s]   (4 edges/thread)
__global__ __launch_bounds__(256)
void k_edge1(const int* __restrict__ ei, int E) {
    cudaGridDependencySynchronize();
    int stride = gridDim.x * blockDim.x;
    int i = blockIdx.x * blockDim.x + threadIdx.x;
    int E4 = E >> 2;
    const int4* s4 = (const int4*)ei;
    const int4* d4 = (const int4*)(ei + E);
    for (int e = i; e < E4; e += stride) {
        int4 s = s4[e];
        int4 d = d4[e];
        float4 h0 = g_hs[s.x];
        float4 h1 = g_hs[s.y];
        float4 h2 = g_hs[s.z];
        float4 h3 = g_hs[s.w];
        red4(&g_agg1[d.x], h0.x, h0.y, h0.z);
        red4(&g_agg1[d.y], h1.x, h1.y, h1.z);
        red4(&g_agg1[d.z], h2.x, h2.y, h2.z);
        red4(&g_agg1[d.w], h3.x, h3.y, h3.z);
    }
    for (int e = (E4 << 2) + i; e < E; e += stride) {
        int s = ei[e], d = ei[E + e];
        float4 h = g_hs[s];
        red4(&g_agg1[d], h.x, h.y, h.z);
    }
}

// K5: finalize layer1: a = agg1*dinv (+b1, relu) -> h2 -> t = h2*dinv.
//     Seed window accumulator g_u with self-loop term t[n] (overwrite).
__global__ void k_final1(const float* __restrict__ b1,
                         const float* __restrict__ W2, int N) {
    cudaGridDependencySynchronize();
    int n = blockIdx.x * blockDim.x + threadIdx.x;
    if (n >= N) return;
    float dv = g_dinv[n];
    float4 a = g_agg1[n];
    float o0 = fmaxf(a.x * dv + __ldg(&b1[0]), 0.0f);
    float o1 = fmaxf(a.y * dv + __ldg(&b1[1]), 0.0f);
    float o2 = fmaxf(a.z * dv + __ldg(&b1[2]), 0.0f);
    float h2 = o0 * __ldg(&W2[0]) + o1 * __ldg(&W2[1]) + o2 * __ldg(&W2[2]);
    float t = h2 * dv;
    g_t[n] = t;
    int r = n & (ILEN - 1);
    if (r < PLEN)
        g_u[(n >> 12) * PLEN + r] = t;
}

// K6: layer-2 scatter, filtered, unnormalized: u[d] += t[s].
__global__ __launch_bounds__(256)
void k_edge2(const int* __restrict__ ei, int E) {
    cudaGridDependencySynchronize();
    int stride = gridDim.x * blockDim.x;
    int i = blockIdx.x * blockDim.x + threadIdx.x;
    int E4 = E >> 2;
    const int4* s4 = (const int4*)ei;
    const int4* d4 = (const int4*)(ei + E);
    for (int e = i; e < E4; e += stride) {
        int4 d = d4[e];
        int r0 = d.x & (ILEN - 1);
        int r1 = d.y & (ILEN - 1);
        int r2 = d.z & (ILEN - 1);
        int r3 = d.w & (ILEN - 1);
        if ((r0 < PLEN) | (r1 < PLEN) | (r2 < PLEN) | (r3 < PLEN)) {
            int4 s = s4[e];
            if (r0 < PLEN) atomicAdd(&g_u[(d.x >> 12) * PLEN + r0], g_t[s.x]);
            if (r1 < PLEN) atomicAdd(&g_u[(d.y >> 12) * PLEN + r1], g_t[s.y]);
            if (r2 < PLEN) atomicAdd(&g_u[(d.z >> 12) * PLEN + r2], g_t[s.z]);
            if (r3 < PLEN) atomicAdd(&g_u[(d.w >> 12) * PLEN + r3], g_t[s.w]);
        }
    }
    for (int e = (E4 << 2) + i; e < E; e += stride) {
        int d = ei[E + e];
        int r = d & (ILEN - 1);
        if (r < PLEN)
            atomicAdd(&g_u[(d >> 12) * PLEN + r], g_t[ei[e]]);
    }
}

// K7: final output: out = u * dinv[node] + b2.  Also re-zeroes g_deg.
__global__ void k_out(const float* __restrict__ b2, float* __restrict__ out,
                      int N) {
    cudaGridDependencySynchronize();
    int i = blockIdx.x * blockDim.x + threadIdx.x;
    if (i < N) g_deg[i] = 0.0f;
    if (i >= WTOT) return;
    int n = (i >> 10) * ILEN + (i & (PLEN - 1));
    out[i] = g_u[i] * g_dinv[n] + __ldg(&b2[0]);
}

// ---------------------------------------------------------------------------
static void launch_pdl(const void* fn, dim3 grid, dim3 block, void** args) {
    cudaLaunchConfig_t cfg = {};
    cfg.gridDim  = grid;
    cfg.blockDim = block;
    cfg.stream   = 0;
    cudaLaunchAttribute attr[1];
    attr[0].id = cudaLaunchAttributeProgrammaticStreamSerialization;
    attr[0].val.programmaticStreamSerializationAllowed = 1;
    cfg.attrs = attr;
    cfg.numAttrs = 1;
    cudaLaunchKernelExC(&cfg, fn, args);
}

extern "C" void kernel_launch(void* const* d_in, const int* in_sizes, int n_in,
                              void* d_out, int out_size) {
    const float* X   = (const float*)d_in[0];   // [N,256]
    const float* W1  = (const float*)d_in[1];   // [256,3]
    const float* b1  = (const float*)d_in[2];   // [3]
    const float* W2  = (const float*)d_in[3];   // [3,1]
    const float* b2  = (const float*)d_in[4];   // [1]
    const int*   ei  = (const int*)d_in[5];     // [2,E]
    float*       out = (float*)d_out;

    int N = in_sizes[0] / 256;
    int E = in_sizes[5] / 2;

    const int T = 256;
    int nb_node = (N + T - 1) / T;

    const int* dstp = ei + E;
    {   // k_fused (g_deg already zero: .bss init / re-zeroed by k_out)
        k_fused<<<GRID_FUSED, T>>>((const longlong2*)X, W1, dstp, N, E);
    }
    {   // k_node
        void* args[] = { &N };
        launch_pdl((const void*)k_node, dim3(nb_node), dim3(T), args);
    }
    {   // k_edge1
        void* args[] = { (void*)&ei, &E };
        launch_pdl((const void*)k_edge1, dim3(4096), dim3(T), args);
    }
    {   // k_final1
        void* args[] = { (void*)&b1, (void*)&W2, &N };
        launch_pdl((const void*)k_final1, dim3(nb_node), dim3(T), args);
    }
    {   // k_edge2
        void* args[] = { (void*)&ei, &E };
        launch_pdl((const void*)k_edge2, dim3(4096), dim3(T), args);
    }
    {   // k_out (covers N threads: zeroes g_deg, writes WTOT outputs)
        void* args[] = { (void*)&b2, (void*)&out, &N };
        launch_pdl((const void*)k_out, dim3(nb_node), dim3(T), args);
    }
}